// round 10
// baseline (speedup 1.0000x reference)
#include <cuda_runtime.h>
#include <cuda_fp16.h>
#include <cstdint>

// ============================================================================
// RBFEuclidean: out[b,u] = ||x_b||^2 - 2 x@w + ||w_u||^2
// x: [65536,256] f32, w: [256,1024] f32, out: [65536,1024] f32
//
// classic mma.sync, compute_103-safe.
// R9: fp16 ACCUMULATION (m16n8k16.f16.f16.f16.f16) with two independent
// accumulator chains (even/odd ks), combined in f32 at epilogue.
// Skeleton = R8: MTILE 128 / NSUB 128 / NT 8, 16 warps, warp tile m32n32.
// ============================================================================

#define THREADS 512
#define MTILE   128
#define NSUB    128
#define NT      8
#define KTOT    256

#define OFF_XSQ    0              // 128 f32 -> 512
#define OFF_WSQ    512            // 1024 f32 -> 4608
#define OFF_STAGE  4608           // 16 warps * 1280B -> 25088
#define OFF_A      25088          // 128 rows * 512B = 65536 -> 90624
#define OFF_B      90624          // 2 * 65536 -> 221696
#define BBUF_BYTES 65536
#define SMEM_BYTES 221696

__device__ __half g_w16[256 * 1024];   // w as [k][n], fp16
__device__ float  g_wsq[1024];

// ---------------------------------------------------------------------------
__device__ __forceinline__ void cp_async16(uint32_t smem_addr, const void* gptr) {
    asm volatile("cp.async.cg.shared.global [%0], [%1], 16;"
                 :: "r"(smem_addr), "l"(__cvta_generic_to_global(gptr)) : "memory");
}
__device__ __forceinline__ void cp_commit() {
    asm volatile("cp.async.commit_group;" ::: "memory");
}
template <int N>
__device__ __forceinline__ void cp_wait() {
    asm volatile("cp.async.wait_group %0;" :: "n"(N) : "memory");
}

__device__ __forceinline__ void ldsm_x4(uint32_t* r, uint32_t addr) {
    asm volatile("ldmatrix.sync.aligned.m8n8.x4.shared.b16 {%0,%1,%2,%3}, [%4];"
                 : "=r"(r[0]), "=r"(r[1]), "=r"(r[2]), "=r"(r[3]) : "r"(addr));
}
__device__ __forceinline__ void ldsm_x4_t(uint32_t* r, uint32_t addr) {
    asm volatile("ldmatrix.sync.aligned.m8n8.x4.trans.shared.b16 {%0,%1,%2,%3}, [%4];"
                 : "=r"(r[0]), "=r"(r[1]), "=r"(r[2]), "=r"(r[3]) : "r"(addr));
}
// fp16-accumulate HMMA: D (f16x2 x2) = A*B + D
__device__ __forceinline__ void mma16816_f16(uint32_t* d, const uint32_t* a, const uint32_t* b) {
    asm volatile(
        "mma.sync.aligned.m16n8k16.row.col.f16.f16.f16.f16 "
        "{%0,%1}, {%2,%3,%4,%5}, {%6,%7}, {%0,%1};"
        : "+r"(d[0]), "+r"(d[1])
        : "r"(a[0]), "r"(a[1]), "r"(a[2]), "r"(a[3]), "r"(b[0]), "r"(b[1]));
}

// ---------------------------------------------------------------------------
// Prep: w -> fp16 copy + w_sq (f32). 64 blocks x 256 threads.
// ---------------------------------------------------------------------------
__global__ void prep_w_kernel(const float* __restrict__ w) {
    int t = blockIdx.x * 256 + threadIdx.x;      // 0..16383
#pragma unroll
    for (int i = 0; i < 16; i++) {
        int idx = t + i * 16384;
        g_w16[idx] = __float2half(w[idx]);
    }
    if (t < 1024) {
        float acc = 0.f;
#pragma unroll 8
        for (int f = 0; f < 256; f++) {
            float v = w[(size_t)f * 1024 + t];
            acc += v * v;
        }
        g_wsq[t] = acc;
    }
}

// ---------------------------------------------------------------------------
struct Frag {
    uint32_t a[2][4];
    uint32_t b[4][2];
};

__device__ __forceinline__ void load_frag(Frag& f, uint32_t aaddr0, uint32_t aaddr1,
                                          int ahi, int asw, uint32_t bbase,
                                          const uint32_t* bofs, int ks) {
    uint32_t swz = (uint32_t)((2 * ks + ahi) ^ asw) << 4;
    ldsm_x4(f.a[0], aaddr0 + swz);
    ldsm_x4(f.a[1], aaddr1 + swz);
#pragma unroll
    for (int p = 0; p < 2; p++) {
        uint32_t r4[4];
        ldsm_x4_t(r4, bbase + (uint32_t)ks * 4096 + bofs[p]);
        f.b[2 * p][0] = r4[0];
        f.b[2 * p][1] = r4[1];
        f.b[2 * p + 1][0] = r4[2];
        f.b[2 * p + 1][1] = r4[3];
    }
}

// ---------------------------------------------------------------------------
// Main kernel
// ---------------------------------------------------------------------------
__global__ void __launch_bounds__(THREADS, 1)
rbf_main_kernel(const float* __restrict__ x, float* __restrict__ out) {
    extern __shared__ char smem[];
    const uint32_t sb = (uint32_t)__cvta_generic_to_shared(smem);
    const int tid = threadIdx.x;
    const int wid = tid >> 5;
    const int lid = tid & 31;
    const int wm = wid >> 2;          // m-warp 0..3 (32 rows each)
    const int wn = wid & 3;           // n-warp 0..3 (32 cols each)
    const size_t m_base = (size_t)blockIdx.x * MTILE;

    // --- prefetch B(0): 4096 x 16B chunks, 8 per thread ---
#pragma unroll
    for (int i = 0; i < 8; i++) {
        int idx = tid + i * 512;
        int k = idx >> 4, c = idx & 15;
        const __half* src = g_w16 + (size_t)k * 1024 + c * 8;
        uint32_t dst = sb + OFF_B + k * 256 + ((c ^ (k & 7)) << 4);
        cp_async16(dst, src);
    }
    cp_commit();

    // --- w_sq to smem ---
    {
        float* wsq_s = (float*)(smem + OFF_WSQ);
        wsq_s[tid] = g_wsq[tid];
        wsq_s[tid + 512] = g_wsq[tid + 512];
    }

    // --- A load: f32 -> fp16 swizzled smem, x_sq in f32 (8 threads/row) ---
    {
        const int lo = tid & 7;
        const int rq = tid >> 3;              // 0..63
        const float4* xv = (const float4*)(x + m_base * KTOT);
        float* xsq_s = (float*)(smem + OFF_XSQ);
#pragma unroll 1
        for (int pass = 0; pass < 2; pass++) {
            int r = pass * 64 + rq;
            int rx = r & 7;
            uint32_t rowbase = (uint32_t)(OFF_A + r * 512);
            float acc = 0.f;
#pragma unroll
            for (int j = 0; j < 8; j++) {
                int c4 = lo + j * 8;          // float4 index 0..63
                float4 v = xv[(size_t)r * 64 + c4];
                acc += v.x * v.x + v.y * v.y + v.z * v.z + v.w * v.w;
                __half2 h0 = __floats2half2_rn(v.x, v.y);
                __half2 h1 = __floats2half2_rn(v.z, v.w);
                uint32_t byte = rowbase + ((uint32_t)((c4 >> 1) ^ rx) << 4) + ((c4 & 1) << 3);
                uint2 u;
                u.x = *(uint32_t*)&h0;
                u.y = *(uint32_t*)&h1;
                *(uint2*)(smem + byte) = u;
            }
            acc += __shfl_xor_sync(0xffffffffu, acc, 1);
            acc += __shfl_xor_sync(0xffffffffu, acc, 2);
            acc += __shfl_xor_sync(0xffffffffu, acc, 4);
            if (lo == 0) xsq_s[r] = acc;
        }
    }

    const float* xsq_s = (const float*)(smem + OFF_XSQ);
    const float* wsq_s = (const float*)(smem + OFF_WSQ);

    // A addressing: rows wm*32 + (lid&15), +16
    const uint32_t aaddr0 = sb + OFF_A + (uint32_t)(wm * 32 + (lid & 15)) * 512;
    const uint32_t aaddr1 = aaddr0 + 16 * 512;
    const int ahi = lid >> 4;
    const int asw = lid & 7;

    // B ldsm offsets: 2 ldsm_x4_t cover n32 (n8 tiles wn*4 .. wn*4+3)
    uint32_t bofs[2];
    {
        int sub = lid >> 3;
#pragma unroll
        for (int p = 0; p < 2; p++) {
            int jl = wn * 4 + 2 * p + (sub >> 1);
            bofs[p] = (uint32_t)((sub & 1) * 2048 + (lid & 7) * 256 + ((jl ^ (lid & 7)) << 4));
        }
    }

    float* stageF = (float*)(smem + OFF_STAGE + wid * 1280);   // 8 rows x 40 f32

    for (int nt = 0; nt < NT; nt++) {
        __syncthreads();   // compute(nt-1) reads done -> buffer (nt+1)&1 free
        if (nt + 1 < NT) {
#pragma unroll
            for (int i = 0; i < 8; i++) {
                int idx = tid + i * 512;
                int k = idx >> 4, c = idx & 15;
                const __half* src = g_w16 + (size_t)k * 1024 + (nt + 1) * NSUB + c * 8;
                uint32_t dst = sb + OFF_B + ((nt + 1) & 1) * BBUF_BYTES
                             + k * 256 + ((c ^ (k & 7)) << 4);
                cp_async16(dst, src);
            }
            cp_commit();
            cp_wait<1>();
        } else {
            cp_wait<0>();
        }
        __syncthreads();   // B(nt) visible

        // Two independent fp16 accumulator chains (even/odd ks)
        uint32_t dA[2][4][2], dB[2][4][2];
#pragma unroll
        for (int mt = 0; mt < 2; mt++)
#pragma unroll
            for (int j = 0; j < 4; j++) {
                dA[mt][j][0] = 0u; dA[mt][j][1] = 0u;
                dB[mt][j][0] = 0u; dB[mt][j][1] = 0u;
            }

        const uint32_t bbase = sb + OFF_B + (nt & 1) * BBUF_BYTES;

        Frag fr[2];
        load_frag(fr[0], aaddr0, aaddr1, ahi, asw, bbase, bofs, 0);
#pragma unroll 4
        for (int ks = 0; ks < 16; ks++) {
            Frag& cur = fr[ks & 1];
            if (ks + 1 < 16)
                load_frag(fr[(ks + 1) & 1], aaddr0, aaddr1, ahi, asw, bbase, bofs, ks + 1);
            if (ks & 1) {
#pragma unroll
                for (int mt = 0; mt < 2; mt++)
#pragma unroll
                    for (int j = 0; j < 4; j++)
                        mma16816_f16(dB[mt][j], cur.a[mt], cur.b[j]);
            } else {
#pragma unroll
                for (int mt = 0; mt < 2; mt++)
#pragma unroll
                    for (int j = 0; j < 4; j++)
                        mma16816_f16(dA[mt][j], cur.a[mt], cur.b[j]);
            }
        }

        // --- epilogue: combine chains in f32, stage, coalesced STG ---
        const int col0 = nt * NSUB + wn * 32;
        const int cql = (lid & 7) * 4;
        const float4 wq = *(const float4*)(wsq_s + col0 + cql);
#pragma unroll 1
        for (int s = 0; s < 4; s++) {
            const int mt = s >> 1, h = s & 1;
#pragma unroll
            for (int j = 0; j < 4; j++) {
                float2 fa = __half22float2(*(const __half2*)&dA[mt][j][h]);
                float2 fb = __half22float2(*(const __half2*)&dB[mt][j][h]);
                *(float2*)&stageF[(lid >> 2) * 40 + j * 8 + (lid & 3) * 2] =
                    make_float2(fa.x + fb.x, fa.y + fb.y);
            }
            __syncwarp();
#pragma unroll
            for (int p = 0; p < 2; p++) {
                int rl = p * 4 + (lid >> 3);
                float4 v = *(const float4*)&stageF[rl * 40 + cql];
                int grow = wm * 32 + s * 8 + rl;
                float xs = xsq_s[grow];
                float4 o;
                o.x = fmaf(-2.f, v.x, xs + wq.x);
                o.y = fmaf(-2.f, v.y, xs + wq.y);
                o.z = fmaf(-2.f, v.z, xs + wq.z);
                o.w = fmaf(-2.f, v.w, xs + wq.w);
                *(float4*)(out + (m_base + grow) * 1024 + col0 + cql) = o;
            }
            __syncwarp();
        }
    }
}

// ---------------------------------------------------------------------------
extern "C" void kernel_launch(void* const* d_in, const int* in_sizes, int n_in,
                              void* d_out, int out_size) {
    (void)in_sizes; (void)n_in; (void)out_size;
    const float* x = (const float*)d_in[0];
    const float* w = (const float*)d_in[1];
    float* out = (float*)d_out;

    cudaFuncSetAttribute(rbf_main_kernel,
                         cudaFuncAttributeMaxDynamicSharedMemorySize, SMEM_BYTES);

    prep_w_kernel<<<64, 256>>>(w);
    rbf_main_kernel<<<512, THREADS, SMEM_BYTES>>>(x, out);
}

// round 11
// speedup vs baseline: 1.4360x; 1.4360x over previous
#include <cuda_runtime.h>
#include <cuda_fp16.h>
#include <cstdint>

// ============================================================================
// RBFEuclidean: out[b,u] = ||x_b||^2 - 2 x@w + ||w_u||^2
// x: [65536,256] f32, w: [256,1024] f32, out: [65536,1024] f32
//
// classic mma.sync (HMMA m16n8k16 fp16->f32), compute_103-safe.
// R11: 2 CTAs per SM (256 thr, ~101KB smem each) so one CTA's mainloop
// overlaps the other's epilogue/barriers. 32 B-phases of [128k x 64n],
// double-buffered cp.async. Direct STG.64 epilogue from fragments (no
// SMEM staging round-trip).
// ============================================================================

#define THREADS 256
#define MTILE   128
#define KTOT    256
#define NPHASE  32            // 16 n-subtiles x 2 k-halves

#define OFF_XSQ    0              // 128 f32 -> 512
#define OFF_WSQ    512            // 1024 f32 -> 4608
#define OFF_A      5120           // 128 rows * 512B = 65536 -> 70656
#define OFF_B      70656          // 2 * 16384 -> 103424
#define BBUF_BYTES 16384
#define SMEM_BYTES 103424

__device__ __half g_w16[256 * 1024];   // w as [k][n], fp16
__device__ float  g_wsq[1024];

// ---------------------------------------------------------------------------
__device__ __forceinline__ void cp_async16(uint32_t smem_addr, const void* gptr) {
    asm volatile("cp.async.cg.shared.global [%0], [%1], 16;"
                 :: "r"(smem_addr), "l"(__cvta_generic_to_global(gptr)) : "memory");
}
__device__ __forceinline__ void cp_commit() {
    asm volatile("cp.async.commit_group;" ::: "memory");
}
template <int N>
__device__ __forceinline__ void cp_wait() {
    asm volatile("cp.async.wait_group %0;" :: "n"(N) : "memory");
}

__device__ __forceinline__ void ldsm_x4(uint32_t* r, uint32_t addr) {
    asm volatile("ldmatrix.sync.aligned.m8n8.x4.shared.b16 {%0,%1,%2,%3}, [%4];"
                 : "=r"(r[0]), "=r"(r[1]), "=r"(r[2]), "=r"(r[3]) : "r"(addr));
}
__device__ __forceinline__ void ldsm_x4_t(uint32_t* r, uint32_t addr) {
    asm volatile("ldmatrix.sync.aligned.m8n8.x4.trans.shared.b16 {%0,%1,%2,%3}, [%4];"
                 : "=r"(r[0]), "=r"(r[1]), "=r"(r[2]), "=r"(r[3]) : "r"(addr));
}
__device__ __forceinline__ void mma16816(float* d, const uint32_t* a, const uint32_t* b) {
    asm volatile(
        "mma.sync.aligned.m16n8k16.row.col.f32.f16.f16.f32 "
        "{%0,%1,%2,%3}, {%4,%5,%6,%7}, {%8,%9}, {%0,%1,%2,%3};"
        : "+f"(d[0]), "+f"(d[1]), "+f"(d[2]), "+f"(d[3])
        : "r"(a[0]), "r"(a[1]), "r"(a[2]), "r"(a[3]), "r"(b[0]), "r"(b[1]));
}

// ---------------------------------------------------------------------------
// Prep: w -> fp16 copy + w_sq (f32). 64 blocks x 256 threads.
// ---------------------------------------------------------------------------
__global__ void prep_w_kernel(const float* __restrict__ w) {
    int t = blockIdx.x * 256 + threadIdx.x;      // 0..16383
#pragma unroll
    for (int i = 0; i < 16; i++) {
        int idx = t + i * 16384;
        g_w16[idx] = __float2half(w[idx]);
    }
    if (t < 1024) {
        float acc = 0.f;
#pragma unroll 8
        for (int f = 0; f < 256; f++) {
            float v = w[(size_t)f * 1024 + t];
            acc += v * v;
        }
        g_wsq[t] = acc;
    }
}

// ---------------------------------------------------------------------------
// B stage prefetch: stage p covers cols (p>>1)*64.., k-half (p&1)*128..
// Layout: 128 k-rows x 128B (64 cols fp16), 16B-chunk swizzle.
// ---------------------------------------------------------------------------
__device__ __forceinline__ void prefetch_b(uint32_t sb, int p, int tid) {
    const int nt = p >> 1, kh = p & 1;
    const uint32_t dbase = sb + OFF_B + (uint32_t)(p & 1 ? BBUF_BYTES * ((p >> 0) & 1) : 0);
    // note: buffer index = p & 1
    const uint32_t bufbase = sb + OFF_B + (uint32_t)((p & 1) * BBUF_BYTES);
    (void)dbase;
#pragma unroll
    for (int i = 0; i < 4; i++) {
        int idx = tid + i * 256;              // 0..1023 16B chunks
        int k = idx >> 3, c = idx & 7;
        const __half* src = g_w16 + (size_t)(kh * 128 + k) * 1024 + nt * 64 + c * 8;
        uint32_t dst = bufbase + k * 128 + ((c ^ (k & 7)) << 4);
        cp_async16(dst, src);
    }
    cp_commit();
}

// ---------------------------------------------------------------------------
// Main kernel: 512 CTAs x 256 threads, 2 CTAs/SM.
// ---------------------------------------------------------------------------
__global__ void __launch_bounds__(THREADS, 2)
rbf_main_kernel(const float* __restrict__ x, float* __restrict__ out) {
    extern __shared__ char smem[];
    const uint32_t sb = (uint32_t)__cvta_generic_to_shared(smem);
    const int tid = threadIdx.x;
    const int wid = tid >> 5;
    const int lid = tid & 31;
    const int wm = wid >> 1;          // m-warp 0..3 (32 rows each)
    const int wn = wid & 1;           // n-warp 0..1 (32 cols each)
    const size_t m_base = (size_t)blockIdx.x * MTILE;

    // --- prefetch B stage 0 ---
    prefetch_b(sb, 0, tid);

    // --- w_sq to smem ---
    {
        float* wsq_s = (float*)(smem + OFF_WSQ);
#pragma unroll
        for (int i = 0; i < 4; i++) wsq_s[tid + i * 256] = g_wsq[tid + i * 256];
    }

    // --- A load: f32 -> fp16 swizzled smem, x_sq in f32 (8 threads/row) ---
    {
        const int lo = tid & 7;
        const int rq = tid >> 3;              // 0..31
        const float4* xv = (const float4*)(x + m_base * KTOT);
        float* xsq_s = (float*)(smem + OFF_XSQ);
#pragma unroll 1
        for (int pass = 0; pass < 4; pass++) {
            int r = pass * 32 + rq;
            int rx = r & 7;
            uint32_t rowbase = (uint32_t)(OFF_A + r * 512);
            float acc = 0.f;
#pragma unroll
            for (int j = 0; j < 8; j++) {
                int c4 = lo + j * 8;          // float4 index 0..63
                float4 v = xv[(size_t)r * 64 + c4];
                acc += v.x * v.x + v.y * v.y + v.z * v.z + v.w * v.w;
                __half2 h0 = __floats2half2_rn(v.x, v.y);
                __half2 h1 = __floats2half2_rn(v.z, v.w);
                uint32_t byte = rowbase + ((uint32_t)((c4 >> 1) ^ rx) << 4) + ((c4 & 1) << 3);
                uint2 u;
                u.x = *(uint32_t*)&h0;
                u.y = *(uint32_t*)&h1;
                *(uint2*)(smem + byte) = u;
            }
            acc += __shfl_xor_sync(0xffffffffu, acc, 1);
            acc += __shfl_xor_sync(0xffffffffu, acc, 2);
            acc += __shfl_xor_sync(0xffffffffu, acc, 4);
            if (lo == 0) xsq_s[r] = acc;
        }
    }

    const float* xsq_s = (const float*)(smem + OFF_XSQ);
    const float* wsq_s = (const float*)(smem + OFF_WSQ);

    // A addressing: rows wm*32 + (lid&15), +16
    const uint32_t aaddr0 = sb + OFF_A + (uint32_t)(wm * 32 + (lid & 15)) * 512;
    const uint32_t aaddr1 = aaddr0 + 16 * 512;
    const int ahi = lid >> 4;
    const int asw = lid & 7;

    // B ldsm offsets: 2 ldsm_x4_t cover n32 (n8 tiles wn*4 .. wn*4+3)
    uint32_t bofs[2];
    {
        int sub = lid >> 3;
#pragma unroll
        for (int p = 0; p < 2; p++) {
            int jl = wn * 4 + 2 * p + (sub >> 1);
            bofs[p] = (uint32_t)((sub & 1) * 1024 + (lid & 7) * 128 + ((jl ^ (lid & 7)) << 4));
        }
    }

    float d[2][4][4];

    for (int p = 0; p < NPHASE; p++) {
        __syncthreads();   // all reads of buffer (p+1)&1 (phase p-1) done
        if (p + 1 < NPHASE) {
            prefetch_b(sb, p + 1, tid);
            cp_wait<1>();
        } else {
            cp_wait<0>();
        }
        __syncthreads();   // stage p visible

        if ((p & 1) == 0) {
#pragma unroll
            for (int mt = 0; mt < 2; mt++)
#pragma unroll
                for (int j = 0; j < 4; j++)
#pragma unroll
                    for (int e = 0; e < 4; e++) d[mt][j][e] = 0.f;
        }

        const uint32_t bbase = sb + OFF_B + (uint32_t)((p & 1) * BBUF_BYTES);
        const int ksbase = (p & 1) * 8;      // global k16 index base

#pragma unroll
        for (int ks = 0; ks < 8; ks++) {
            uint32_t a[2][4];
            uint32_t swz = (uint32_t)((2 * (ksbase + ks) + ahi) ^ asw) << 4;
            ldsm_x4(a[0], aaddr0 + swz);
            ldsm_x4(a[1], aaddr1 + swz);
            uint32_t b[4][2];
#pragma unroll
            for (int q = 0; q < 2; q++) {
                uint32_t r4[4];
                ldsm_x4_t(r4, bbase + (uint32_t)ks * 2048 + bofs[q]);
                b[2 * q][0] = r4[0];
                b[2 * q][1] = r4[1];
                b[2 * q + 1][0] = r4[2];
                b[2 * q + 1][1] = r4[3];
            }
#pragma unroll
            for (int mt = 0; mt < 2; mt++)
#pragma unroll
                for (int j = 0; j < 4; j++)
                    mma16816(d[mt][j], a[mt], b[j]);
        }

        if (p & 1) {
            // --- epilogue: direct STG.64 from fragments, no staging ---
            const int col0 = (p >> 1) * 64 + wn * 32;
            const int cb = (lid & 3) * 2;
            float2 wq[4];
#pragma unroll
            for (int j = 0; j < 4; j++)
                wq[j] = *(const float2*)(wsq_s + col0 + j * 8 + cb);
#pragma unroll
            for (int mt = 0; mt < 2; mt++)
#pragma unroll
                for (int h = 0; h < 2; h++) {
                    int grow = wm * 32 + mt * 16 + h * 8 + (lid >> 2);
                    float xs = xsq_s[grow];
                    float* orow = out + (m_base + grow) * 1024 + col0 + cb;
#pragma unroll
                    for (int j = 0; j < 4; j++) {
                        float2 o;
                        o.x = fmaf(-2.f, d[mt][j][2 * h], xs + wq[j].x);
                        o.y = fmaf(-2.f, d[mt][j][2 * h + 1], xs + wq[j].y);
                        *(float2*)(orow + j * 8) = o;
                    }
                }
        }
    }
}

// ---------------------------------------------------------------------------
extern "C" void kernel_launch(void* const* d_in, const int* in_sizes, int n_in,
                              void* d_out, int out_size) {
    (void)in_sizes; (void)n_in; (void)out_size;
    const float* x = (const float*)d_in[0];
    const float* w = (const float*)d_in[1];
    float* out = (float*)d_out;

    cudaFuncSetAttribute(rbf_main_kernel,
                         cudaFuncAttributeMaxDynamicSharedMemorySize, SMEM_BYTES);

    prep_w_kernel<<<64, 256>>>(w);
    rbf_main_kernel<<<512, THREADS, SMEM_BYTES>>>(x, out);
}

// round 12
// speedup vs baseline: 1.5258x; 1.0625x over previous
#include <cuda_runtime.h>
#include <cuda_fp16.h>
#include <cstdint>

// ============================================================================
// RBFEuclidean: out[b,u] = ||x_b||^2 - 2 x@w + ||w_u||^2
// x: [65536,256] f32, w: [256,1024] f32, out: [65536,1024] f32
//
// classic mma.sync (HMMA m16n8k16 fp16->f32), compute_103-safe.
// R12: 2 CTAs/SM (proven R11) + warp tile m32n64 over [64k x 128n] phases
// (6 ldsm : 16 mma, 25% less L1 traffic) + ONE __syncthreads per phase.
// K in 4 quarters; epilogue (direct STG.64) every 4th phase.
// ============================================================================

#define THREADS 256
#define MTILE   128
#define KTOT    256
#define NPHASE  32            // 8 n-tiles x 4 k-quarters

#define OFF_XSQ    0              // 128 f32 -> 512
#define OFF_WSQ    512            // 1024 f32 -> 4608
#define OFF_A      5120           // 128 rows * 512B = 65536 -> 70656
#define OFF_B      70656          // 2 * 16384 -> 103424
#define BBUF_BYTES 16384
#define SMEM_BYTES 103424

__device__ __half g_w16[256 * 1024];   // w as [k][n], fp16
__device__ float  g_wsq[1024];

// ---------------------------------------------------------------------------
__device__ __forceinline__ void cp_async16(uint32_t smem_addr, const void* gptr) {
    asm volatile("cp.async.cg.shared.global [%0], [%1], 16;"
                 :: "r"(smem_addr), "l"(__cvta_generic_to_global(gptr)) : "memory");
}
__device__ __forceinline__ void cp_commit() {
    asm volatile("cp.async.commit_group;" ::: "memory");
}
template <int N>
__device__ __forceinline__ void cp_wait() {
    asm volatile("cp.async.wait_group %0;" :: "n"(N) : "memory");
}

__device__ __forceinline__ void ldsm_x4(uint32_t* r, uint32_t addr) {
    asm volatile("ldmatrix.sync.aligned.m8n8.x4.shared.b16 {%0,%1,%2,%3}, [%4];"
                 : "=r"(r[0]), "=r"(r[1]), "=r"(r[2]), "=r"(r[3]) : "r"(addr));
}
__device__ __forceinline__ void ldsm_x4_t(uint32_t* r, uint32_t addr) {
    asm volatile("ldmatrix.sync.aligned.m8n8.x4.trans.shared.b16 {%0,%1,%2,%3}, [%4];"
                 : "=r"(r[0]), "=r"(r[1]), "=r"(r[2]), "=r"(r[3]) : "r"(addr));
}
__device__ __forceinline__ void mma16816(float* d, const uint32_t* a, const uint32_t* b) {
    asm volatile(
        "mma.sync.aligned.m16n8k16.row.col.f32.f16.f16.f32 "
        "{%0,%1,%2,%3}, {%4,%5,%6,%7}, {%8,%9}, {%0,%1,%2,%3};"
        : "+f"(d[0]), "+f"(d[1]), "+f"(d[2]), "+f"(d[3])
        : "r"(a[0]), "r"(a[1]), "r"(a[2]), "r"(a[3]), "r"(b[0]), "r"(b[1]));
}

// ---------------------------------------------------------------------------
// Prep: w -> fp16 copy + w_sq (f32). 64 blocks x 256 threads.
// ---------------------------------------------------------------------------
__global__ void prep_w_kernel(const float* __restrict__ w) {
    int t = blockIdx.x * 256 + threadIdx.x;      // 0..16383
#pragma unroll
    for (int i = 0; i < 16; i++) {
        int idx = t + i * 16384;
        g_w16[idx] = __float2half(w[idx]);
    }
    if (t < 1024) {
        float acc = 0.f;
#pragma unroll 8
        for (int f = 0; f < 256; f++) {
            float v = w[(size_t)f * 1024 + t];
            acc += v * v;
        }
        g_wsq[t] = acc;
    }
}

// ---------------------------------------------------------------------------
// B stage prefetch: stage s covers cols (s>>2)*128.., k-rows (s&3)*64..
// Buffer layout: 64 k-rows x 256B (128 cols fp16), 16B-chunk swizzle.
// ---------------------------------------------------------------------------
__device__ __forceinline__ void prefetch_b(uint32_t sb, int s, int tid) {
    const int nt = s >> 2, kq = s & 3;
    const uint32_t bufbase = sb + OFF_B + (uint32_t)((s & 1) * BBUF_BYTES);
#pragma unroll
    for (int i = 0; i < 4; i++) {
        int idx = tid + i * 256;              // 0..1023 16B chunks
        int k = idx >> 4, c = idx & 15;       // k-row 0..63, chunk 0..15
        const __half* src = g_w16 + (size_t)(kq * 64 + k) * 1024 + nt * 128 + c * 8;
        uint32_t dst = bufbase + k * 256 + ((c ^ (k & 7)) << 4);
        cp_async16(dst, src);
    }
    cp_commit();
}

// ---------------------------------------------------------------------------
// Main kernel: 512 CTAs x 256 threads, 2 CTAs/SM.
// ---------------------------------------------------------------------------
__global__ void __launch_bounds__(THREADS, 2)
rbf_main_kernel(const float* __restrict__ x, float* __restrict__ out) {
    extern __shared__ char smem[];
    const uint32_t sb = (uint32_t)__cvta_generic_to_shared(smem);
    const int tid = threadIdx.x;
    const int wid = tid >> 5;
    const int lid = tid & 31;
    const int wm = wid >> 1;          // m-warp 0..3 (32 rows each)
    const int wn = wid & 1;           // n-warp 0..1 (64 cols each)
    const size_t m_base = (size_t)blockIdx.x * MTILE;

    // --- prefetch B stage 0 ---
    prefetch_b(sb, 0, tid);

    // --- w_sq to smem ---
    {
        float* wsq_s = (float*)(smem + OFF_WSQ);
#pragma unroll
        for (int i = 0; i < 4; i++) wsq_s[tid + i * 256] = g_wsq[tid + i * 256];
    }

    // --- A load: f32 -> fp16 swizzled smem, x_sq in f32 (8 threads/row) ---
    {
        const int lo = tid & 7;
        const int rq = tid >> 3;              // 0..31
        const float4* xv = (const float4*)(x + m_base * KTOT);
        float* xsq_s = (float*)(smem + OFF_XSQ);
#pragma unroll 1
        for (int pass = 0; pass < 4; pass++) {
            int r = pass * 32 + rq;
            int rx = r & 7;
            uint32_t rowbase = (uint32_t)(OFF_A + r * 512);
            float acc = 0.f;
#pragma unroll
            for (int j = 0; j < 8; j++) {
                int c4 = lo + j * 8;          // float4 index 0..63
                float4 v = xv[(size_t)r * 64 + c4];
                acc += v.x * v.x + v.y * v.y + v.z * v.z + v.w * v.w;
                __half2 h0 = __floats2half2_rn(v.x, v.y);
                __half2 h1 = __floats2half2_rn(v.z, v.w);
                uint32_t byte = rowbase + ((uint32_t)((c4 >> 1) ^ rx) << 4) + ((c4 & 1) << 3);
                uint2 u;
                u.x = *(uint32_t*)&h0;
                u.y = *(uint32_t*)&h1;
                *(uint2*)(smem + byte) = u;
            }
            acc += __shfl_xor_sync(0xffffffffu, acc, 1);
            acc += __shfl_xor_sync(0xffffffffu, acc, 2);
            acc += __shfl_xor_sync(0xffffffffu, acc, 4);
            if (lo == 0) xsq_s[r] = acc;
        }
    }

    const float* xsq_s = (const float*)(smem + OFF_XSQ);
    const float* wsq_s = (const float*)(smem + OFF_WSQ);

    // A addressing: rows wm*32 + (lid&15), +16
    const uint32_t aaddr0 = sb + OFF_A + (uint32_t)(wm * 32 + (lid & 15)) * 512;
    const uint32_t aaddr1 = aaddr0 + 16 * 512;
    const int ahi = lid >> 4;
    const int asw = lid & 7;

    // B ldsm offsets: 4 ldsm_x4_t cover n64 (n8 tiles wn*8 .. wn*8+7)
    // buffer rows 256B; k8-half = 8 rows = 2048B
    uint32_t bofs[4];
    {
        int sub = lid >> 3;
#pragma unroll
        for (int q = 0; q < 4; q++) {
            int jl = wn * 8 + 2 * q + (sub >> 1);
            bofs[q] = (uint32_t)((sub & 1) * 2048 + (lid & 7) * 256 + ((jl ^ (lid & 7)) << 4));
        }
    }

    // publish stage 0, issue stage 1
    cp_wait<0>();
    __syncthreads();
    prefetch_b(sb, 1, tid);

    float d[2][8][4];

    for (int p = 0; p < NPHASE; p++) {
        const int kq = p & 3;
        if (kq == 0) {
#pragma unroll
            for (int mt = 0; mt < 2; mt++)
#pragma unroll
                for (int j = 0; j < 8; j++)
#pragma unroll
                    for (int e = 0; e < 4; e++) d[mt][j][e] = 0.f;
        }

        const uint32_t bbase = sb + OFF_B + (uint32_t)((p & 1) * BBUF_BYTES);

#pragma unroll
        for (int ksl = 0; ksl < 4; ksl++) {
            const int ks = kq * 4 + ksl;     // global k16 index for A
            uint32_t a[2][4];
            uint32_t swz = (uint32_t)((2 * ks + ahi) ^ asw) << 4;
            ldsm_x4(a[0], aaddr0 + swz);
            ldsm_x4(a[1], aaddr1 + swz);
            uint32_t b[8][2];
#pragma unroll
            for (int q = 0; q < 4; q++) {
                uint32_t r4[4];
                ldsm_x4_t(r4, bbase + (uint32_t)ksl * 4096 + bofs[q]);
                b[2 * q][0] = r4[0];
                b[2 * q][1] = r4[1];
                b[2 * q + 1][0] = r4[2];
                b[2 * q + 1][1] = r4[3];
            }
#pragma unroll
            for (int mt = 0; mt < 2; mt++)
#pragma unroll
                for (int j = 0; j < 8; j++)
                    mma16816(d[mt][j], a[mt], b[j]);
        }

        if (kq == 3) {
            // --- epilogue: direct STG.64 from fragments ---
            const int col0 = (p >> 2) * 128 + wn * 64;
            const int cb = (lid & 3) * 2;
            float2 wq[8];
#pragma unroll
            for (int j = 0; j < 8; j++)
                wq[j] = *(const float2*)(wsq_s + col0 + j * 8 + cb);
#pragma unroll
            for (int mt = 0; mt < 2; mt++)
#pragma unroll
                for (int h = 0; h < 2; h++) {
                    int grow = wm * 32 + mt * 16 + h * 8 + (lid >> 2);
                    float xs = xsq_s[grow];
                    float* orow = out + (m_base + grow) * 1024 + col0 + cb;
#pragma unroll
                    for (int j = 0; j < 8; j++) {
                        float2 o;
                        o.x = fmaf(-2.f, d[mt][j][2 * h], xs + wq[j].x);
                        o.y = fmaf(-2.f, d[mt][j][2 * h + 1], xs + wq[j].y);
                        *(float2*)(orow + j * 8) = o;
                    }
                }
        }

        if (p + 1 < NPHASE) {
            cp_wait<0>();        // stage p+1 (issued a full phase ago) complete
            __syncthreads();     // publish stage p+1; all reads of buf[p&1] done
            if (p + 2 < NPHASE)
                prefetch_b(sb, p + 2, tid);   // into just-freed buf[p&1]
        }
    }
}

// ---------------------------------------------------------------------------
extern "C" void kernel_launch(void* const* d_in, const int* in_sizes, int n_in,
                              void* d_out, int out_size) {
    (void)in_sizes; (void)n_in; (void)out_size;
    const float* x = (const float*)d_in[0];
    const float* w = (const float*)d_in[1];
    float* out = (float*)d_out;

    cudaFuncSetAttribute(rbf_main_kernel,
                         cudaFuncAttributeMaxDynamicSharedMemorySize, SMEM_BYTES);

    prep_w_kernel<<<64, 256>>>(w);
    rbf_main_kernel<<<512, THREADS, SMEM_BYTES>>>(x, out);
}